// round 6
// baseline (speedup 1.0000x reference)
#include <cuda_runtime.h>
#include <math.h>
#include <stdint.h>

#define NJ 34
#define NV 500000
#define NB 32
#define NQF (NV * 3 / 4)       // 375000 output float4s per batch plane
#define BLK 256
#define NBLOCKS ((NV + BLK - 1) / BLK)   // 1954
#define F4_PER_BLK (BLK * 3 / 4)         // 192 float4s per plane per block
#define W_STRIDE 1088                     // floats of weights per warp (32*34)

__constant__ int c_parents[NJ] = {
    -1, 0, 1, 2, 2, 4, 5, 6, 7, 8, 9, 7, 11, 12, 7, 14, 15, 2,
    17, 18, 19, 20, 21, 22, 20, 24, 25, 20, 27, 28, 0, 30, 0, 32
};

#define FMA2(d, a, b) \
    asm("fma.rn.f32x2 %0, %1, %2, %3;" : "=l"(d) : "l"(a), "l"(b), "l"(d))

__global__ __launch_bounds__(BLK) void fused_lbs_kernel(
    const float* __restrict__ pose,
    const float* __restrict__ joints,
    const float* __restrict__ weights,
    const float* __restrict__ v_template,
    const float* __restrict__ local_adjust,
    const float* __restrict__ disp,
    const float* __restrict__ scale,
    const float* __restrict__ est,
    float4* __restrict__ out)
{
    __shared__ __align__(16) float sA[NJ * 12];
    __shared__ float sBase[NB * 4];
    __shared__ __align__(16) float sW[8 * W_STRIDE];   // 34 KB weight staging
    __shared__ __align__(16) float sVP[BLK * 3];       // 3 KB posed verts

    // phase-0 scratch aliased inside sW (dead until phase 1)
    float* sT = sW;           // NJ*12 = 408 floats
    float* sJ = sW + 512;     // NJ*3

    const int t = threadIdx.x;
    const int w = t >> 5;
    const int l = t & 31;

    // ---- phase 0a: base table + joints ----
    if (t < NB * 3) {
        int b = t / 3, cc = t - b * 3;
        sBase[b * 4 + cc] = disp[cc] + est[t];
    } else if (t >= 96 && t < 96 + NB) {
        sBase[(t - 96) * 4 + 3] = 0.0f;
    }
    if (t < NJ * 3) sJ[t] = joints[t];
    __syncthreads();

    // ---- phase 0b: local transforms ----
    if (t < NJ) {
        float rx = pose[t * 3 + 0], ry = pose[t * 3 + 1], rz = pose[t * 3 + 2];
        float ang = sqrtf(rx * rx + ry * ry + rz * rz + 1e-8f);
        float inv = 1.0f / ang;
        float x = rx * inv, y = ry * inv, z = rz * inv;
        float s = sinf(ang), c = cosf(ang), oc = 1.0f - c;
        int p = c_parents[t];
        float tx = sJ[t * 3 + 0], ty = sJ[t * 3 + 1], tz = sJ[t * 3 + 2];
        if (p >= 0) { tx -= sJ[p * 3 + 0]; ty -= sJ[p * 3 + 1]; tz -= sJ[p * 3 + 2]; }
        float* T = sT + t * 12;
        T[0] = c + oc * x * x;      T[1] = oc * x * y - s * z;  T[2]  = oc * x * z + s * y;  T[3]  = tx;
        T[4] = oc * x * y + s * z;  T[5] = c + oc * y * y;      T[6]  = oc * y * z - s * x;  T[7]  = ty;
        T[8] = oc * x * z - s * y;  T[9] = oc * y * z + s * x;  T[10] = c + oc * z * z;      T[11] = tz;
    }
    __syncthreads();

    // ---- phase 0c: ancestor-chain composition -> A (scale folded) ----
    if (t < NJ) {
        int chain[16];
        int d = 0;
        for (int n = t; n >= 0; n = c_parents[n]) chain[d++] = n;
        float G[12];
        const float* Tr = sT + chain[d - 1] * 12;
        #pragma unroll
        for (int k = 0; k < 12; k++) G[k] = Tr[k];
        for (int k = d - 2; k >= 0; k--) {
            const float* Tc = sT + chain[k] * 12;
            float C[12];
            #pragma unroll
            for (int r = 0; r < 3; r++) {
                float g0 = G[r * 4 + 0], g1 = G[r * 4 + 1], g2 = G[r * 4 + 2], g3 = G[r * 4 + 3];
                C[r * 4 + 0] = g0 * Tc[0] + g1 * Tc[4] + g2 * Tc[8];
                C[r * 4 + 1] = g0 * Tc[1] + g1 * Tc[5] + g2 * Tc[9];
                C[r * 4 + 2] = g0 * Tc[2] + g1 * Tc[6] + g2 * Tc[10];
                C[r * 4 + 3] = g0 * Tc[3] + g1 * Tc[7] + g2 * Tc[11] + g3;
            }
            #pragma unroll
            for (int k2 = 0; k2 < 12; k2++) G[k2] = C[k2];
        }
        float sc = scale[0];
        float jx = sJ[t * 3 + 0], jy = sJ[t * 3 + 1], jz = sJ[t * 3 + 2];
        #pragma unroll
        for (int r = 0; r < 3; r++) {
            float tr = G[r * 4 + 0] * jx + G[r * 4 + 1] * jy + G[r * 4 + 2] * jz;
            sA[t * 12 + r * 4 + 0] = sc * G[r * 4 + 0];
            sA[t * 12 + r * 4 + 1] = sc * G[r * 4 + 1];
            sA[t * 12 + r * 4 + 2] = sc * G[r * 4 + 2];
            sA[t * 12 + r * 4 + 3] = sc * (G[r * 4 + 3] - tr);
        }
    }
    __syncthreads();   // sT/sJ dead; sW free for weight staging

    // ---- phase 1a: warp-cooperative coalesced weight staging ----
    const int block_base = blockIdx.x * BLK;
    const int warp_base = block_base + w * 32;
    const int v = block_base + t;

    if (warp_base < NV) {
        const size_t f4_base = (size_t)warp_base * 34 / 4;
        const size_t f4_total = (size_t)NV * 34 / 4;
        const float4* srcw = (const float4*)weights;
        float4* dstw = (float4*)(sW + w * W_STRIDE);
        #pragma unroll
        for (int i = 0; i < 9; i++) {
            int idx = i * 32 + l;
            if (idx < 272 && f4_base + idx < f4_total)
                dstw[idx] = __ldcs(srcw + f4_base + idx);
        }
    }
    __syncwarp();

    // ---- phase 1b: skin with packed f32x2 FMA ----
    float vp0 = 0.0f, vp1 = 0.0f, vp2 = 0.0f;
    if (v < NV) {
        unsigned long long T2[6];
        #pragma unroll
        for (int k = 0; k < 6; k++) T2[k] = 0ull;

        const float2* wp = (const float2*)(sW + w * W_STRIDE + l * 34);
        #pragma unroll
        for (int k = 0; k < 17; k++) {
            float2 w2 = wp[k];
            {
                uint32_t wi = __float_as_uint(w2.x);
                unsigned long long wpk;
                asm("mov.b64 %0, {%1, %1};" : "=l"(wpk) : "r"(wi));
                const ulonglong2* Ap = (const ulonglong2*)(sA + (2 * k) * 12);
                ulonglong2 q0 = Ap[0], q1 = Ap[1], q2 = Ap[2];
                FMA2(T2[0], wpk, q0.x); FMA2(T2[1], wpk, q0.y);
                FMA2(T2[2], wpk, q1.x); FMA2(T2[3], wpk, q1.y);
                FMA2(T2[4], wpk, q2.x); FMA2(T2[5], wpk, q2.y);
            }
            {
                uint32_t wi = __float_as_uint(w2.y);
                unsigned long long wpk;
                asm("mov.b64 %0, {%1, %1};" : "=l"(wpk) : "r"(wi));
                const ulonglong2* Ap = (const ulonglong2*)(sA + (2 * k + 1) * 12);
                ulonglong2 q0 = Ap[0], q1 = Ap[1], q2 = Ap[2];
                FMA2(T2[0], wpk, q0.x); FMA2(T2[1], wpk, q0.y);
                FMA2(T2[2], wpk, q1.x); FMA2(T2[3], wpk, q1.y);
                FMA2(T2[4], wpk, q2.x); FMA2(T2[5], wpk, q2.y);
            }
        }

        float T[12];
        #pragma unroll
        for (int i = 0; i < 6; i++) {
            uint32_t lo, hi;
            asm("mov.b64 {%0, %1}, %2;" : "=r"(lo), "=r"(hi) : "l"(T2[i]));
            T[2 * i + 0] = __uint_as_float(lo);
            T[2 * i + 1] = __uint_as_float(hi);
        }

        const float* vtp = v_template + (size_t)v * 3;
        const float* lap = local_adjust + (size_t)v * 3;
        float vx = __ldcs(vtp + 0) + __ldcs(lap + 0);
        float vy = __ldcs(vtp + 1) + __ldcs(lap + 1);
        float vz = __ldcs(vtp + 2) + __ldcs(lap + 2);

        vp0 = T[0] * vx + T[1] * vy + T[2]  * vz + T[3];
        vp1 = T[4] * vx + T[5] * vy + T[6]  * vz + T[7];
        vp2 = T[8] * vx + T[9] * vy + T[10] * vz + T[11];
    }

    // ---- phase 2: stage + balanced batched stores ----
    __syncthreads();
    sVP[t * 3 + 0] = vp0;
    sVP[t * 3 + 1] = vp1;
    sVP[t * 3 + 2] = vp2;
    __syncthreads();

    // warp w owns planes 4w..4w+3; lane l stores f4s r = i*32+l, i=0..5
    const int block_f4 = blockIdx.x * F4_PER_BLK;
    const int b0i = w * 4;
    float bx[4], by[4], bz[4];
    #pragma unroll
    for (int p = 0; p < 4; p++) {
        bx[p] = sBase[(b0i + p) * 4 + 0];
        by[p] = sBase[(b0i + p) * 4 + 1];
        bz[p] = sBase[(b0i + p) * 4 + 2];
    }
    const float4* sVP4 = (const float4*)sVP;

    #pragma unroll
    for (int i = 0; i < 6; i++) {
        int r = i * 32 + l;
        if (block_f4 + r < NQF) {
            float4 pv = sVP4[r];
            int m = r % 3;
            #pragma unroll
            for (int p = 0; p < 4; p++) {
                float s0 = (m == 0) ? bx[p] : ((m == 1) ? by[p] : bz[p]);
                float s1 = (m == 0) ? by[p] : ((m == 1) ? bz[p] : bx[p]);
                float s2 = (m == 0) ? bz[p] : ((m == 1) ? bx[p] : by[p]);
                float4 o;
                o.x = pv.x + s0; o.y = pv.y + s1; o.z = pv.z + s2; o.w = pv.w + s0;
                __stcs(out + (size_t)(b0i + p) * NQF + block_f4 + r, o);
            }
        }
    }
}

// ---------------------------------------------------------------------------
extern "C" void kernel_launch(void* const* d_in, const int* in_sizes, int n_in,
                              void* d_out, int out_size)
{
    const float* pose         = (const float*)d_in[0]; // (34,3)
    const float* joints       = (const float*)d_in[1]; // (34,3)
    const float* weights      = (const float*)d_in[2]; // (V,34)
    const float* v_template   = (const float*)d_in[3]; // (V,3)
    const float* local_adjust = (const float*)d_in[4]; // (V,3)
    const float* displacement = (const float*)d_in[5]; // (1,3)
    const float* scale        = (const float*)d_in[6]; // (1,)
    const float* est          = (const float*)d_in[7]; // (B,3)
    float* out = (float*)d_out;
    (void)in_sizes; (void)n_in; (void)out_size;

    fused_lbs_kernel<<<NBLOCKS, BLK>>>(pose, joints, weights, v_template,
                                       local_adjust, displacement, scale, est,
                                       (float4*)out);
}